// round 4
// baseline (speedup 1.0000x reference)
#include <cuda_runtime.h>
#include <math.h>
#include <stdint.h>

// Problem constants
#define C_DIM 64
#define D_DIM 32
#define H_DIM 96
#define W_DIM 96
#define B_DIM 2
#define WT 8          // w-tile per block
#define NTHREADS 512

// smem layout (floats)
#define SV_OFF    0       // phase A/B: x tile [64][264]=16896 ; after sync: V [8 w][*2308] = 18464
#define SQ_OFF    18464   // Q [8 w (*1156)][32 d (*36)][q] : 9248
#define SK_OFF    27712   // K : 9248
#define SAT_OFF   36960   // attn [8 w (*1152)][32 d (*36)][e] : 9216
#define SAW_OFF   46176   // prepacked W A-fragments: 8192
#define SBIAS_OFF 54368   // 128
#define SPOS_OFF  54496   // 1024
#define SMEM_FLOATS 55520
#define SMEM_BYTES (SMEM_FLOATS * 4)
// sout (output staging) reuses SQ..SK region: sout[c*257+n], 64*257=16448 <= 18496

__device__ float g_tb[32];

__device__ __forceinline__ float tf32r(float x) {
    uint32_t u;
    asm("cvt.rna.tf32.f32 %0, %1;" : "=r"(u) : "f"(x));
    return __uint_as_float(u);
}

__device__ __forceinline__ void mma_tf32(float* d, const float4& a, uint32_t b0, uint32_t b1) {
    const uint32_t* A = reinterpret_cast<const uint32_t*>(&a);
    asm volatile(
        "mma.sync.aligned.m16n8k8.row.col.f32.tf32.tf32.f32 "
        "{%0,%1,%2,%3}, {%4,%5,%6,%7}, {%8,%9}, {%0,%1,%2,%3};"
        : "+f"(d[0]), "+f"(d[1]), "+f"(d[2]), "+f"(d[3])
        : "r"(A[0]), "r"(A[1]), "r"(A[2]), "r"(A[3]), "r"(b0), "r"(b1));
}

// ---------------------------------------------------------------------------
// Kernel 0: text bias
// ---------------------------------------------------------------------------
__global__ void text_bias_kernel(const float* __restrict__ text_emb,
                                 const float* __restrict__ wt,
                                 const float* __restrict__ bt) {
    __shared__ float mcol[256];
    int t = threadIdx.x;
    float s = 0.f;
    #pragma unroll
    for (int r = 0; r < 32; ++r) s += text_emb[r * 256 + t];
    mcol[t] = s * (1.0f / 32.0f);
    __syncthreads();
    int warp = t >> 5, lane = t & 31;
    for (int q = warp; q < 32; q += 8) {
        float acc = 0.f;
        #pragma unroll
        for (int k = 0; k < 8; ++k) acc += wt[q * 256 + lane + k * 32] * mcol[lane + k * 32];
        #pragma unroll
        for (int o = 16; o > 0; o >>= 1) acc += __shfl_xor_sync(0xffffffffu, acc, o);
        if (lane == 0) g_tb[q] = acc + bt[q];
    }
}

// ---------------------------------------------------------------------------
// Main fused kernel: one block per (b, h, w-tile of 8)
// ---------------------------------------------------------------------------
__global__ __launch_bounds__(NTHREADS, 1)
void attn_kernel(const float* __restrict__ x,
                 const float* __restrict__ wq, const float* __restrict__ bq,
                 const float* __restrict__ wk, const float* __restrict__ bk,
                 const float* __restrict__ wv, const float* __restrict__ bv,
                 const float* __restrict__ pos, const float* __restrict__ gamma,
                 float* __restrict__ out) {
    extern __shared__ float sm[];
    float* sxv   = sm + SV_OFF;   // x tile (phase A/B), V fragments afterwards
    float* sq    = sm + SQ_OFF;
    float* sk    = sm + SK_OFF;
    float* sat   = sm + SAT_OFF;
    float* saw   = sm + SAW_OFF;
    float* sbias = sm + SBIAS_OFF;
    float* spos  = sm + SPOS_OFF;
    float* sout  = sm + SQ_OFF;   // staging reuse

    const int tid = threadIdx.x;
    const int bid = blockIdx.x;
    const int nwT = W_DIM / WT;   // 12
    const int b   = bid / (H_DIM * nwT);
    const int rem = bid % (H_DIM * nwT);
    const int h   = rem / nwT;
    const int w0  = (rem % nwT) * WT;

    const int HW = H_DIM * W_DIM; // 9216
    const size_t base = (size_t)b * C_DIM * D_DIM * HW + (size_t)h * W_DIM + w0;

    // ---- Phase A: loads ----
    #pragma unroll
    for (int it = 0; it < 8; ++it) {
        int i = tid + it * NTHREADS;           // 4096 float4s
        int c = i >> 6, d = (i >> 1) & 31, w2 = i & 1;
        float4 v = *reinterpret_cast<const float4*>(x + base + ((size_t)c * D_DIM + d) * HW + w2 * 4);
        v.x = tf32r(v.x); v.y = tf32r(v.y); v.z = tf32r(v.z); v.w = tf32r(v.w);
        *reinterpret_cast<float4*>(&sxv[c * 264 + d * 8 + w2 * 4]) = v;
    }
    // W prepacked into A-fragment order (validated in R3):
    // saw[((mt*8+kt)*32 + lane)*4 + v] = W[mt*16 + g + (v&1)*8][kt*8 + t + (v>>1)*4]
    #pragma unroll
    for (int it = 0; it < 16; ++it) {
        int idx = tid + it * NTHREADS;         // 8192 elems
        int v    = idx & 3;
        int lane = (idx >> 2) & 31;
        int kt   = (idx >> 7) & 7;
        int mt   = idx >> 10;
        int g = lane >> 2, t = lane & 3;
        int o = mt * 16 + g + (v & 1) * 8;
        int c = kt * 8 + t + (v >> 1) * 4;
        float wval;
        if (o < 32)       wval = wq[o * 64 + c];
        else if (o < 64)  wval = wk[(o - 32) * 64 + c];
        else              wval = wv[(o - 64) * 64 + c];
        saw[idx] = tf32r(wval);
    }
    if (tid < 128) {
        float bb;
        if (tid < 32)      bb = bq[tid] + g_tb[tid];
        else if (tid < 64) bb = bk[tid - 32] + g_tb[tid - 32];
        else               bb = bv[tid - 64];
        sbias[tid] = bb;
    }
    #pragma unroll
    for (int it = 0; it < 2; ++it) spos[tid + it * NTHREADS] = pos[tid + it * NTHREADS];
    __syncthreads();

    // ---- Phase B: tf32 MMA GEMM  C[128 o][256 n] = W[128,64] * X[64,256] ----
    const int warp = tid >> 5, lane = tid & 31;
    const int mw = warp & 3;        // 0:Q 1:K 2:V(c0-31) 3:V(c32-63)
    const int nw = warp >> 2;       // n quarter (64 wide)
    const int g = lane >> 2, t = lane & 3;

    {
        float acc[2][8][4];
        #pragma unroll
        for (int s_ = 0; s_ < 2; ++s_)
            #pragma unroll
            for (int nt = 0; nt < 8; ++nt)
                #pragma unroll
                for (int v = 0; v < 4; ++v) acc[s_][nt][v] = 0.f;

        #pragma unroll
        for (int kt = 0; kt < 8; ++kt) {
            float4 a0 = *reinterpret_cast<const float4*>(&saw[((mw * 2 + 0) * 8 + kt) * 128 + lane * 4]);
            float4 a1 = *reinterpret_cast<const float4*>(&saw[((mw * 2 + 1) * 8 + kt) * 128 + lane * 4]);
            const float* xb0 = &sxv[(kt * 8 + t) * 264 + nw * 64 + g];
            const float* xb1 = &sxv[(kt * 8 + t + 4) * 264 + nw * 64 + g];
            #pragma unroll
            for (int nt = 0; nt < 8; ++nt) {
                uint32_t b0 = __float_as_uint(xb0[nt * 8]);
                uint32_t b1 = __float_as_uint(xb1[nt * 8]);
                mma_tf32(acc[0][nt], a0, b0, b1);
                mma_tf32(acc[1][nt], a1, b0, b1);
            }
        }

        // Q/K epilogue -> sq/sk[w*1156 + d*36 + q], tf32-rounded; softmax scale folded into Q
        if (mw < 2) {
            float* dst = (mw == 0) ? sq : sk;
            const float qscale = (mw == 0) ? 0.17677669529663687f : 1.0f;
            #pragma unroll
            for (int s_ = 0; s_ < 2; ++s_) {
                #pragma unroll
                for (int nt = 0; nt < 8; ++nt) {
                    int d = nw * 8 + nt;
                    #pragma unroll
                    for (int v = 0; v < 4; ++v) {
                        int q = s_ * 16 + g + (v >> 1) * 8;
                        int w = 2 * t + (v & 1);
                        float val = acc[s_][nt][v] + sbias[mw * 32 + q] + spos[q * 32 + d];
                        dst[w * 1156 + d * 36 + q] = tf32r(val * qscale);
                    }
                }
            }
        }
        __syncthreads();   // all X reads done; V warps may overwrite sxv region

        // V epilogue -> sv[w*2308 + c*36 + e], tf32-rounded (A-operand layout for phase D)
        if (mw >= 2) {
            #pragma unroll
            for (int s_ = 0; s_ < 2; ++s_) {
                #pragma unroll
                for (int nt = 0; nt < 8; ++nt) {
                    int e = nw * 8 + nt;
                    #pragma unroll
                    for (int v = 0; v < 4; ++v) {
                        int cch = (mw - 2) * 32 + s_ * 16 + g + (v >> 1) * 8;
                        int w = 2 * t + (v & 1);
                        sxv[w * 2308 + cch * 36 + e] = tf32r(acc[s_][nt][v] + sbias[64 + cch]);
                    }
                }
            }
        }
    }

    // ---- Phase C: scores via MMA + fragment softmax. warp = (w, d-half) ----
    const int aw = warp >> 1;
    const int dh = (warp & 1) * 16;
    {
        const float* qb = &sq[aw * 1156 + dh * 36];
        const float* kb = &sk[aw * 1156];

        float4 afr[4];
        #pragma unroll
        for (int kt = 0; kt < 4; ++kt) {
            afr[kt].x = qb[g * 36 + kt * 8 + t];
            afr[kt].y = qb[(g + 8) * 36 + kt * 8 + t];
            afr[kt].z = qb[g * 36 + kt * 8 + t + 4];
            afr[kt].w = qb[(g + 8) * 36 + kt * 8 + t + 4];
        }

        float fs[4][4];
        #pragma unroll
        for (int nt = 0; nt < 4; ++nt)
            #pragma unroll
            for (int v = 0; v < 4; ++v) fs[nt][v] = 0.f;

        #pragma unroll
        for (int nt = 0; nt < 4; ++nt) {
            #pragma unroll
            for (int kt = 0; kt < 4; ++kt) {
                uint32_t b0 = __float_as_uint(kb[(nt * 8 + g) * 36 + kt * 8 + t]);
                uint32_t b1 = __float_as_uint(kb[(nt * 8 + g) * 36 + kt * 8 + t + 4]);
                mma_tf32(fs[nt], afr[kt], b0, b1);
            }
        }
        // fs[nt][v]: S[d = dh + g + (v>>1)*8][e = nt*8 + 2t + (v&1)] (already scaled via Q)

        // softmax over e: row0 = dh+g (v=0,1), row1 = dh+g+8 (v=2,3); quad = lanes sharing g
        float m0 = -1e30f, m1 = -1e30f;
        #pragma unroll
        for (int nt = 0; nt < 4; ++nt) {
            m0 = fmaxf(m0, fmaxf(fs[nt][0], fs[nt][1]));
            m1 = fmaxf(m1, fmaxf(fs[nt][2], fs[nt][3]));
        }
        m0 = fmaxf(m0, __shfl_xor_sync(0xffffffffu, m0, 1));
        m0 = fmaxf(m0, __shfl_xor_sync(0xffffffffu, m0, 2));
        m1 = fmaxf(m1, __shfl_xor_sync(0xffffffffu, m1, 1));
        m1 = fmaxf(m1, __shfl_xor_sync(0xffffffffu, m1, 2));

        float s0 = 0.f, s1 = 0.f;
        #pragma unroll
        for (int nt = 0; nt < 4; ++nt) {
            fs[nt][0] = __expf(fs[nt][0] - m0); s0 += fs[nt][0];
            fs[nt][1] = __expf(fs[nt][1] - m0); s0 += fs[nt][1];
            fs[nt][2] = __expf(fs[nt][2] - m1); s1 += fs[nt][2];
            fs[nt][3] = __expf(fs[nt][3] - m1); s1 += fs[nt][3];
        }
        s0 += __shfl_xor_sync(0xffffffffu, s0, 1);
        s0 += __shfl_xor_sync(0xffffffffu, s0, 2);
        s1 += __shfl_xor_sync(0xffffffffu, s1, 1);
        s1 += __shfl_xor_sync(0xffffffffu, s1, 2);
        float inv0 = __fdividef(1.f, s0);
        float inv1 = __fdividef(1.f, s1);

        float* satw = &sat[aw * 1152];
        #pragma unroll
        for (int nt = 0; nt < 4; ++nt) {
            int e = nt * 8 + 2 * t;
            satw[(dh + g) * 36 + e]         = tf32r(fs[nt][0] * inv0);
            satw[(dh + g) * 36 + e + 1]     = tf32r(fs[nt][1] * inv0);
            satw[(dh + g + 8) * 36 + e]     = tf32r(fs[nt][2] * inv1);
            satw[(dh + g + 8) * 36 + e + 1] = tf32r(fs[nt][3] * inv1);
        }
    }
    __syncthreads();   // sv (V) + sat complete

    // ---- Phase D: out[c][d] = V[c][e] @ attn[d][e]^T via MMA. warp = (w, c-half) ----
    {
        const int cb = (warp & 1) * 32;
        const float* vb = &sxv[aw * 2308 + cb * 36];
        const float* ab = &sat[aw * 1152];

        float4 av[2][4];
        #pragma unroll
        for (int mt = 0; mt < 2; ++mt) {
            #pragma unroll
            for (int kt = 0; kt < 4; ++kt) {
                av[mt][kt].x = vb[(mt * 16 + g) * 36 + kt * 8 + t];
                av[mt][kt].y = vb[(mt * 16 + g + 8) * 36 + kt * 8 + t];
                av[mt][kt].z = vb[(mt * 16 + g) * 36 + kt * 8 + t + 4];
                av[mt][kt].w = vb[(mt * 16 + g + 8) * 36 + kt * 8 + t + 4];
            }
        }

        float od[2][4][4];
        #pragma unroll
        for (int mt = 0; mt < 2; ++mt)
            #pragma unroll
            for (int nt = 0; nt < 4; ++nt)
                #pragma unroll
                for (int v = 0; v < 4; ++v) od[mt][nt][v] = 0.f;

        #pragma unroll
        for (int nt = 0; nt < 4; ++nt) {
            #pragma unroll
            for (int kt = 0; kt < 4; ++kt) {
                uint32_t b0 = __float_as_uint(ab[(nt * 8 + g) * 36 + kt * 8 + t]);
                uint32_t b1 = __float_as_uint(ab[(nt * 8 + g) * 36 + kt * 8 + t + 4]);
                mma_tf32(od[0][nt], av[0][kt], b0, b1);
                mma_tf32(od[1][nt], av[1][kt], b0, b1);
            }
        }
        // od[mt][nt][v]: out[c = cb + mt*16 + g + (v>>1)*8][d = nt*8 + 2t + (v&1)]

        #pragma unroll
        for (int mt = 0; mt < 2; ++mt) {
            #pragma unroll
            for (int nt = 0; nt < 4; ++nt) {
                #pragma unroll
                for (int v = 0; v < 4; ++v) {
                    int c = cb + mt * 16 + g + (v >> 1) * 8;
                    int d = nt * 8 + 2 * t + (v & 1);
                    sout[c * 257 + d * 8 + aw] = od[mt][nt][v];
                }
            }
        }
    }
    __syncthreads();

    // ---- Epilogue: out = g*attn_out + (1-g)*x, coalesced ----
    const float gm = gamma[0];
    const float g_  = 1.f / (1.f + __expf(-gm));
    const float g1 = 1.f - g_;
    #pragma unroll
    for (int it = 0; it < 8; ++it) {
        int i = tid + it * NTHREADS;
        int c = i >> 6, d = (i >> 1) & 31, w2 = i & 1;
        size_t gaddr = base + ((size_t)c * D_DIM + d) * HW + w2 * 4;
        float4 xv = *reinterpret_cast<const float4*>(x + gaddr);
        const float* sp = &sout[c * 257 + d * 8 + w2 * 4];
        float4 r;
        r.x = g_ * sp[0] + g1 * xv.x;
        r.y = g_ * sp[1] + g1 * xv.y;
        r.z = g_ * sp[2] + g1 * xv.z;
        r.w = g_ * sp[3] + g1 * xv.w;
        *reinterpret_cast<float4*>(out + gaddr) = r;
    }
}

// ---------------------------------------------------------------------------
extern "C" void kernel_launch(void* const* d_in, const int* in_sizes, int n_in,
                              void* d_out, int out_size) {
    const float* x        = (const float*)d_in[0];
    const float* text_emb = (const float*)d_in[1];
    const float* wq       = (const float*)d_in[2];
    const float* bq       = (const float*)d_in[3];
    const float* wk       = (const float*)d_in[4];
    const float* bk       = (const float*)d_in[5];
    const float* wv       = (const float*)d_in[6];
    const float* bv       = (const float*)d_in[7];
    const float* wt       = (const float*)d_in[8];
    const float* bt       = (const float*)d_in[9];
    const float* pos      = (const float*)d_in[10];
    const float* gamma    = (const float*)d_in[11];
    float* out = (float*)d_out;

    cudaFuncSetAttribute(attn_kernel, cudaFuncAttributeMaxDynamicSharedMemorySize, SMEM_BYTES);

    text_bias_kernel<<<1, 256>>>(text_emb, wt, bt);

    const int grid = B_DIM * H_DIM * (W_DIM / WT);  // 2304
    attn_kernel<<<grid, NTHREADS, SMEM_BYTES>>>(x, wq, bq, wk, bk, wv, bv, pos, gamma, out);
}

// round 5
// speedup vs baseline: 1.1506x; 1.1506x over previous
#include <cuda_runtime.h>
#include <math.h>
#include <stdint.h>

// Problem constants
#define C_DIM 64
#define D_DIM 32
#define H_DIM 96
#define W_DIM 96
#define B_DIM 2
#define WT 4          // w-tile per block
#define NTHREADS 256

// smem layout (floats), all offsets 16B-aligned
#define SV_OFF    0       // phase A/B: x tile [64][136]=8704 ; after mid-B sync: V [4 w(*2309)][c(*36)][e] = 9226
#define SQ_OFF    9240    // Q [4 w (*1185)][32 q (*36)][d] : 4740
#define SK_OFF    13984   // K : 4740
#define SAW_OFF   18728   // W A-fragments 8192 ; after phase B: attn [4 w(*1152)][e(*36)][d] = 4608
#define SBIAS_OFF 26920   // 128
#define SPOS_OFF  27048   // 1024
#define SMEM_FLOATS 28072
#define SMEM_BYTES (SMEM_FLOATS * 4)   // 112288 B = 109.7 KB -> 2 CTAs/SM
// sout staging overlays SQ..SK: sout[c*132 + w*32 + d], 64*132 = 8448 <= 9488

__device__ float g_tb[32];
__device__ float g_wpack[8192];   // prepacked tf32 W in A-fragment order

__device__ __forceinline__ float tf32r(float x) {
    uint32_t u;
    asm("cvt.rna.tf32.f32 %0, %1;" : "=r"(u) : "f"(x));
    return __uint_as_float(u);
}

__device__ __forceinline__ void mma_tf32(float* d, const float4& a, uint32_t b0, uint32_t b1) {
    const uint32_t* A = reinterpret_cast<const uint32_t*>(&a);
    asm volatile(
        "mma.sync.aligned.m16n8k8.row.col.f32.tf32.tf32.f32 "
        "{%0,%1,%2,%3}, {%4,%5,%6,%7}, {%8,%9}, {%0,%1,%2,%3};"
        : "+f"(d[0]), "+f"(d[1]), "+f"(d[2]), "+f"(d[3])
        : "r"(A[0]), "r"(A[1]), "r"(A[2]), "r"(A[3]), "r"(b0), "r"(b1));
}

// ---------------------------------------------------------------------------
// Setup kernel: text bias + weight prepack (fragment order, tf32-rounded)
// ---------------------------------------------------------------------------
__global__ void setup_kernel(const float* __restrict__ text_emb,
                             const float* __restrict__ wt,
                             const float* __restrict__ bt,
                             const float* __restrict__ wq,
                             const float* __restrict__ wk,
                             const float* __restrict__ wv) {
    __shared__ float mcol[256];
    int t = threadIdx.x;
    float s = 0.f;
    #pragma unroll
    for (int r = 0; r < 32; ++r) s += text_emb[r * 256 + t];
    mcol[t] = s * (1.0f / 32.0f);
    __syncthreads();
    int warp = t >> 5, lane = t & 31;
    for (int q = warp; q < 32; q += 8) {
        float acc = 0.f;
        #pragma unroll
        for (int k = 0; k < 8; ++k) acc += wt[q * 256 + lane + k * 32] * mcol[lane + k * 32];
        #pragma unroll
        for (int o = 16; o > 0; o >>= 1) acc += __shfl_xor_sync(0xffffffffu, acc, o);
        if (lane == 0) g_tb[q] = acc + bt[q];
    }
    // weight prepack: g_wpack[((mt*8+kt)*32 + lane)*4 + v] = W[mt*16+g+(v&1)*8][kt*8+tt+(v>>1)*4]
    #pragma unroll
    for (int it = 0; it < 32; ++it) {
        int idx  = t + it * 256;
        int v    = idx & 3;
        int ln   = (idx >> 2) & 31;
        int kt   = (idx >> 7) & 7;
        int mt   = idx >> 10;
        int g = ln >> 2, tt = ln & 3;
        int o = mt * 16 + g + (v & 1) * 8;
        int c = kt * 8 + tt + (v >> 1) * 4;
        float wval;
        if (o < 32)       wval = wq[o * 64 + c];
        else if (o < 64)  wval = wk[(o - 32) * 64 + c];
        else              wval = wv[(o - 64) * 64 + c];
        g_wpack[idx] = tf32r(wval);
    }
}

// ---------------------------------------------------------------------------
// Main fused kernel: one block per (b, h, w-tile of 4); 256 threads, 2 CTA/SM
// ---------------------------------------------------------------------------
__global__ __launch_bounds__(NTHREADS, 2)
void attn_kernel(const float* __restrict__ x,
                 const float* __restrict__ bq, const float* __restrict__ bk,
                 const float* __restrict__ bv,
                 const float* __restrict__ pos, const float* __restrict__ gamma,
                 float* __restrict__ out) {
    extern __shared__ float sm[];
    float* sxv   = sm + SV_OFF;    // x tile (A/B), V fragments afterwards
    float* sq    = sm + SQ_OFF;
    float* sk    = sm + SK_OFF;
    float* saw   = sm + SAW_OFF;   // W frags (phase B); attn (phases C/D)
    float* sat   = sm + SAW_OFF;
    float* sbias = sm + SBIAS_OFF;
    float* spos  = sm + SPOS_OFF;
    float* sout  = sm + SQ_OFF;    // staging reuse

    const int tid = threadIdx.x;
    const int bid = blockIdx.x;
    const int nwT = W_DIM / WT;   // 24
    const int b   = bid / (H_DIM * nwT);
    const int rem = bid % (H_DIM * nwT);
    const int h   = rem / nwT;
    const int w0  = (rem % nwT) * WT;

    const int HW = H_DIM * W_DIM; // 9216
    const size_t base = (size_t)b * C_DIM * D_DIM * HW + (size_t)h * W_DIM + w0;

    // ---- Phase A: loads ----
    // x tile: one float4 per (c,d) covering w0..w0+3 -> sxv[c*136 + d*4]
    #pragma unroll
    for (int it = 0; it < 8; ++it) {
        int i = tid + it * NTHREADS;          // 2048 float4s
        int c = i >> 5, d = i & 31;
        float4 v = *reinterpret_cast<const float4*>(x + base + ((size_t)c * D_DIM + d) * HW);
        v.x = tf32r(v.x); v.y = tf32r(v.y); v.z = tf32r(v.z); v.w = tf32r(v.w);
        *reinterpret_cast<float4*>(&sxv[c * 136 + d * 4]) = v;
    }
    // prepacked weights: coalesced copy g_wpack -> saw
    #pragma unroll
    for (int it = 0; it < 8; ++it) {
        int i = tid + it * NTHREADS;          // 2048 float4s
        *reinterpret_cast<float4*>(&saw[i * 4]) =
            *reinterpret_cast<const float4*>(&g_wpack[i * 4]);
    }
    if (tid < 128) {
        float bb;
        if (tid < 32)      bb = bq[tid] + g_tb[tid];
        else if (tid < 64) bb = bk[tid - 32] + g_tb[tid - 32];
        else               bb = bv[tid - 64];
        sbias[tid] = bb;
    }
    #pragma unroll
    for (int it = 0; it < 4; ++it) spos[tid + it * NTHREADS] = pos[tid + it * NTHREADS];
    __syncthreads();

    // ---- Phase B: tf32 MMA GEMM  C[128 o][128 n] = W[128,64] * X[64,128] ----
    const int warp = tid >> 5, lane = tid & 31;
    const int mw = warp & 3;        // 0:Q 1:K 2:V(c0-31) 3:V(c32-63)
    const int nh = warp >> 2;       // n half (64 wide)
    const int g = lane >> 2, t = lane & 3;

    {
        float acc[2][8][4];
        #pragma unroll
        for (int s_ = 0; s_ < 2; ++s_)
            #pragma unroll
            for (int nt = 0; nt < 8; ++nt)
                #pragma unroll
                for (int v = 0; v < 4; ++v) acc[s_][nt][v] = 0.f;

        #pragma unroll
        for (int kt = 0; kt < 8; ++kt) {
            float4 a0 = *reinterpret_cast<const float4*>(&saw[((mw * 2 + 0) * 8 + kt) * 128 + lane * 4]);
            float4 a1 = *reinterpret_cast<const float4*>(&saw[((mw * 2 + 1) * 8 + kt) * 128 + lane * 4]);
            const float* xb0 = &sxv[(kt * 8 + t) * 136 + nh * 64 + g];
            const float* xb1 = &sxv[(kt * 8 + t + 4) * 136 + nh * 64 + g];
            #pragma unroll
            for (int nt = 0; nt < 8; ++nt) {
                uint32_t b0 = __float_as_uint(xb0[nt * 8]);
                uint32_t b1 = __float_as_uint(xb1[nt * 8]);
                mma_tf32(acc[0][nt], a0, b0, b1);
                mma_tf32(acc[1][nt], a1, b0, b1);
            }
        }

        // Q/K epilogue -> sq/sk[w*1185 + q*36 + d] (conflict-free), scale folded into Q
        if (mw < 2) {
            float* dst = (mw == 0) ? sq : sk;
            const float qscale = (mw == 0) ? 0.17677669529663687f : 1.0f;
            #pragma unroll
            for (int s_ = 0; s_ < 2; ++s_) {
                #pragma unroll
                for (int nt = 0; nt < 8; ++nt) {
                    #pragma unroll
                    for (int v = 0; v < 4; ++v) {
                        int q = s_ * 16 + g + (v >> 1) * 8;
                        int n = nh * 64 + nt * 8 + 2 * t + (v & 1);
                        int d = n >> 2, w = n & 3;
                        float val = acc[s_][nt][v] + sbias[mw * 32 + q] + spos[q * 32 + d];
                        dst[w * 1185 + q * 36 + d] = tf32r(val * qscale);
                    }
                }
            }
        }
        __syncthreads();   // X reads + saw reads done; V may overwrite sxv, attn may overwrite saw

        // V epilogue -> sv[w*2309 + c*36 + e] (odd w-stride: conflict-free)
        if (mw >= 2) {
            #pragma unroll
            for (int s_ = 0; s_ < 2; ++s_) {
                #pragma unroll
                for (int nt = 0; nt < 8; ++nt) {
                    #pragma unroll
                    for (int v = 0; v < 4; ++v) {
                        int cch = (mw - 2) * 32 + s_ * 16 + g + (v >> 1) * 8;
                        int n = nh * 64 + nt * 8 + 2 * t + (v & 1);
                        int e = n >> 2, w = n & 3;
                        sxv[w * 2309 + cch * 36 + e] = tf32r(acc[s_][nt][v] + sbias[64 + cch]);
                    }
                }
            }
        }
    }

    // ---- Phase C: scores via MMA + fragment softmax. warp = (w, d-half) ----
    const int aw = warp >> 1;           // w index 0..3
    const int dh = (warp & 1) * 16;
    {
        const float* qb = &sq[aw * 1185];   // [q*36 + d]
        const float* kb = &sk[aw * 1185];   // [q*36 + e]

        float4 afr[4];
        #pragma unroll
        for (int kt = 0; kt < 4; ++kt) {    // A[m=d][k=q]
            afr[kt].x = qb[(kt * 8 + t) * 36 + dh + g];
            afr[kt].y = qb[(kt * 8 + t) * 36 + dh + g + 8];
            afr[kt].z = qb[(kt * 8 + t + 4) * 36 + dh + g];
            afr[kt].w = qb[(kt * 8 + t + 4) * 36 + dh + g + 8];
        }

        float fs[4][4];
        #pragma unroll
        for (int nt = 0; nt < 4; ++nt)
            #pragma unroll
            for (int v = 0; v < 4; ++v) fs[nt][v] = 0.f;

        #pragma unroll
        for (int nt = 0; nt < 4; ++nt) {
            #pragma unroll
            for (int kt = 0; kt < 4; ++kt) {   // B[k=q][n=e]
                uint32_t b0 = __float_as_uint(kb[(kt * 8 + t) * 36 + nt * 8 + g]);
                uint32_t b1 = __float_as_uint(kb[(kt * 8 + t + 4) * 36 + nt * 8 + g]);
                mma_tf32(fs[nt], afr[kt], b0, b1);
            }
        }
        // fs[nt][v]: S[d = dh + g + (v>>1)*8][e = nt*8 + 2t + (v&1)]

        float m0 = -1e30f, m1 = -1e30f;
        #pragma unroll
        for (int nt = 0; nt < 4; ++nt) {
            m0 = fmaxf(m0, fmaxf(fs[nt][0], fs[nt][1]));
            m1 = fmaxf(m1, fmaxf(fs[nt][2], fs[nt][3]));
        }
        m0 = fmaxf(m0, __shfl_xor_sync(0xffffffffu, m0, 1));
        m0 = fmaxf(m0, __shfl_xor_sync(0xffffffffu, m0, 2));
        m1 = fmaxf(m1, __shfl_xor_sync(0xffffffffu, m1, 1));
        m1 = fmaxf(m1, __shfl_xor_sync(0xffffffffu, m1, 2));

        float s0 = 0.f, s1 = 0.f;
        #pragma unroll
        for (int nt = 0; nt < 4; ++nt) {
            fs[nt][0] = __expf(fs[nt][0] - m0); s0 += fs[nt][0];
            fs[nt][1] = __expf(fs[nt][1] - m0); s0 += fs[nt][1];
            fs[nt][2] = __expf(fs[nt][2] - m1); s1 += fs[nt][2];
            fs[nt][3] = __expf(fs[nt][3] - m1); s1 += fs[nt][3];
        }
        s0 += __shfl_xor_sync(0xffffffffu, s0, 1);
        s0 += __shfl_xor_sync(0xffffffffu, s0, 2);
        s1 += __shfl_xor_sync(0xffffffffu, s1, 1);
        s1 += __shfl_xor_sync(0xffffffffu, s1, 2);
        float inv0 = __fdividef(1.f, s0);
        float inv1 = __fdividef(1.f, s1);

        // transposed attn store: sat[w*1152 + e*36 + d] (banks 8t+g: conflict-free)
        float* satw = &sat[aw * 1152];
        #pragma unroll
        for (int nt = 0; nt < 4; ++nt) {
            int e = nt * 8 + 2 * t;
            satw[e * 36 + dh + g]           = tf32r(fs[nt][0] * inv0);
            satw[(e + 1) * 36 + dh + g]     = tf32r(fs[nt][1] * inv0);
            satw[e * 36 + dh + g + 8]       = tf32r(fs[nt][2] * inv1);
            satw[(e + 1) * 36 + dh + g + 8] = tf32r(fs[nt][3] * inv1);
        }
    }
    __syncthreads();   // V + attn complete; sq/sk dead -> sout

    // ---- Phase D: out[c][d] = V[c][e] @ attn[e][d] via MMA. warp = (w, c-half) ----
    {
        const int cb = (warp & 1) * 32;
        const float* vb = &sxv[aw * 2309 + cb * 36];   // [c*36 + e]
        const float* ab = &sat[aw * 1152];             // [e*36 + d]

        float4 av[2][4];
        #pragma unroll
        for (int mt = 0; mt < 2; ++mt) {   // A[m=c][k=e]
            #pragma unroll
            for (int kt = 0; kt < 4; ++kt) {
                av[mt][kt].x = vb[(mt * 16 + g) * 36 + kt * 8 + t];
                av[mt][kt].y = vb[(mt * 16 + g + 8) * 36 + kt * 8 + t];
                av[mt][kt].z = vb[(mt * 16 + g) * 36 + kt * 8 + t + 4];
                av[mt][kt].w = vb[(mt * 16 + g + 8) * 36 + kt * 8 + t + 4];
            }
        }

        float od[2][4][4];
        #pragma unroll
        for (int mt = 0; mt < 2; ++mt)
            #pragma unroll
            for (int nt = 0; nt < 4; ++nt)
                #pragma unroll
                for (int v = 0; v < 4; ++v) od[mt][nt][v] = 0.f;

        #pragma unroll
        for (int nt = 0; nt < 4; ++nt) {
            #pragma unroll
            for (int kt = 0; kt < 4; ++kt) {   // B[k=e][n=d]
                uint32_t b0 = __float_as_uint(ab[(kt * 8 + t) * 36 + nt * 8 + g]);
                uint32_t b1 = __float_as_uint(ab[(kt * 8 + t + 4) * 36 + nt * 8 + g]);
                mma_tf32(od[0][nt], av[0][kt], b0, b1);
                mma_tf32(od[1][nt], av[1][kt], b0, b1);
            }
        }
        // od[mt][nt][v]: out[c = cb+mt*16+g+(v>>1)*8][d = nt*8 + 2t + (v&1)]

        // sout[c*132 + w*32 + d], float2 over d-pairs (banks 2g+t bijective: conflict-free)
        #pragma unroll
        for (int mt = 0; mt < 2; ++mt) {
            #pragma unroll
            for (int nt = 0; nt < 4; ++nt) {
                int c0 = cb + mt * 16 + g;
                int d0 = nt * 8 + 2 * t;
                *reinterpret_cast<float2*>(&sout[c0 * 132 + aw * 32 + d0]) =
                    make_float2(od[mt][nt][0], od[mt][nt][1]);
                *reinterpret_cast<float2*>(&sout[(c0 + 8) * 132 + aw * 32 + d0]) =
                    make_float2(od[mt][nt][2], od[mt][nt][3]);
            }
        }
    }
    __syncthreads();

    // ---- Epilogue: out = g*attn_out + (1-g)*x, coalesced ----
    const float gm = gamma[0];
    const float g_ = 1.f / (1.f + __expf(-gm));
    const float g1 = 1.f - g_;
    #pragma unroll
    for (int it = 0; it < 8; ++it) {
        int i = tid + it * NTHREADS;
        int c = i >> 5, d = i & 31;
        size_t gaddr = base + ((size_t)c * D_DIM + d) * HW;
        float4 xv = *reinterpret_cast<const float4*>(x + gaddr);
        float4 r;
        r.x = g_ * sout[c * 132 +  0 + d] + g1 * xv.x;
        r.y = g_ * sout[c * 132 + 32 + d] + g1 * xv.y;
        r.z = g_ * sout[c * 132 + 64 + d] + g1 * xv.z;
        r.w = g_ * sout[c * 132 + 96 + d] + g1 * xv.w;
        *reinterpret_cast<float4*>(out + gaddr) = r;
    }
}

// ---------------------------------------------------------------------------
extern "C" void kernel_launch(void* const* d_in, const int* in_sizes, int n_in,
                              void* d_out, int out_size) {
    const float* x        = (const float*)d_in[0];
    const float* text_emb = (const float*)d_in[1];
    const float* wq       = (const float*)d_in[2];
    const float* bq       = (const float*)d_in[3];
    const float* wk       = (const float*)d_in[4];
    const float* bk       = (const float*)d_in[5];
    const float* wv       = (const float*)d_in[6];
    const float* bv       = (const float*)d_in[7];
    const float* wt       = (const float*)d_in[8];
    const float* bt       = (const float*)d_in[9];
    const float* pos      = (const float*)d_in[10];
    const float* gamma    = (const float*)d_in[11];
    float* out = (float*)d_out;

    cudaFuncSetAttribute(attn_kernel, cudaFuncAttributeMaxDynamicSharedMemorySize, SMEM_BYTES);

    setup_kernel<<<1, 256>>>(text_emb, wt, bt, wq, wk, wv);

    const int grid = B_DIM * H_DIM * (W_DIM / WT);  // 4608
    attn_kernel<<<grid, NTHREADS, SMEM_BYTES>>>(x, bq, bk, bv, pos, gamma, out);
}